// round 12
// baseline (speedup 1.0000x reference)
#include <cuda_runtime.h>
#include <cstdint>

// ============================================================================
// tf32 mma.sync implicit-GEMM 3x3 SAME conv + bias, x-row-resident,
// A-register-reuse version. R12: direct-to-areg LDG (no uint4 temps) + split
// A-prefetch around the nx=0 MMA block to cut register pressure / spills and
// lengthen L2-latency cover.
// CTA: 128 out-channels x 256 px (4 p-rows x 64 q). 8 warps; warp = 64k x 64px
// (two 32-px halves sharing A registers). Per c-chunk (32 c): x strip
// (32c x 6rows x pitch76, halo cols zeroed) in smem; 9 shifts read at (kh,kw)
// offsets. W prepacked in mma-fragment order. B fed as raw f32 bits.
// ============================================================================

#define NSTAGES 36

// [stage36][j4][mtile8][lane32][reg4] tf32 bits
static __device__ __align__(128) unsigned WtFrag[NSTAGES * 4 * 8 * 32 * 4];

__global__ void prepack_kernel(const float* __restrict__ W) {
    int idx = blockIdx.x * 256 + threadIdx.x;
    if (idx >= NSTAGES * 4096) return;
    int reg  = idx & 3;
    int lane = (idx >> 2) & 31;
    int mt   = (idx >> 7) & 7;
    int j    = (idx >> 10) & 3;
    int s    = idx >> 12;            // stage = shift*4 + chunk
    int shift = s >> 2;
    int chunk = s & 3;
    int dr = (reg & 1) ? 8 : 0;
    int dk = (reg & 2) ? 4 : 0;
    int r  = (lane >> 2) + dr;
    int kc = (lane & 3) + dk;
    int k  = mt * 16 + r;
    int c  = chunk * 32 + j * 8 + kc;
    float v = W[k * 1152 + c * 9 + shift];
    unsigned u;
    asm("cvt.rna.tf32.f32 %0, %1;" : "=r"(u) : "f"(v));
    WtFrag[idx] = u;
}

// x strip: [c 0..31][row 0..5][col 0..75]; data cols 4..67 (q+4), halos 3 & 68.
#define XS_PITCH  76
#define XS_ROWS   6
#define XS_BUF_F  (32 * XS_ROWS * XS_PITCH)   // 14592 floats
#define XS_BUF_B  (XS_BUF_F * 4)              // 58368 bytes
#define DYN_SMEM  (2 * XS_BUF_B)              // 116736

__device__ __forceinline__ uint32_t smem_u32(const void* p) {
    uint32_t a;
    asm("{ .reg .u64 t; cvta.to.shared.u64 t, %1; cvt.u32.u64 %0, t; }" : "=r"(a) : "l"(p));
    return a;
}

__device__ __forceinline__ void mma_tf32(float* c, const unsigned* a, const unsigned* b) {
    asm volatile(
        "mma.sync.aligned.m16n8k8.row.col.f32.tf32.tf32.f32 "
        "{%0,%1,%2,%3}, {%4,%5,%6,%7}, {%8,%9}, {%0,%1,%2,%3};"
        : "+f"(c[0]), "+f"(c[1]), "+f"(c[2]), "+f"(c[3])
        : "r"(a[0]), "r"(a[1]), "r"(a[2]), "r"(a[3]), "r"(b[0]), "r"(b[1]));
}

// LDG.128 straight into 4 named regs (no uint4 temp)
#define LDG_A4(dst, ptr) \
    asm volatile("ld.global.nc.v4.u32 {%0,%1,%2,%3}, [%4];" \
                 : "=r"((dst)[0]), "=r"((dst)[1]), "=r"((dst)[2]), "=r"((dst)[3]) \
                 : "l"(ptr))

__global__ __launch_bounds__(256, 1)
void conv_mma_kernel(const float* __restrict__ x,
                     const float* __restrict__ per,
                     float* __restrict__ out) {
    extern __shared__ char smem[];
    const uint32_t sb = smem_u32(smem);

    const int tid  = threadIdx.x;
    const int lane = tid & 31;
    const int w    = tid >> 5;
    const int wm   = w >> 2;           // 0..1 : k base wm*64
    const int wn   = w & 3;            // 0..3 : p-row index within CTA
    const int gid  = lane >> 2;        // 0..7
    const int tig  = lane & 3;         // 0..3

    const int n  = blockIdx.x >> 4;
    const int p0 = (blockIdx.x & 15) << 2;   // 4 p-rows per CTA

    const float* xn = x + (size_t)n * 128 * 4096;

    // ---- zero halo columns (cols 3 and 68 of every (c,row), both buffers) ----
    for (int idx = tid; idx < 2 * 32 * XS_ROWS; idx += 256) {
        const int buf = idx >= 32 * XS_ROWS;
        const int rem = buf ? idx - 32 * XS_ROWS : idx;
        const uint32_t a = sb + buf * XS_BUF_B + rem * (XS_PITCH * 4);
        asm volatile("st.shared.f32 [%0], %1;" :: "r"(a + 3 * 4), "f"(0.f));
        asm volatile("st.shared.f32 [%0], %1;" :: "r"(a + 68 * 4), "f"(0.f));
    }

    // ---- chunk prefetch: 6 rows x 2 x 16B cp.async per thread ----
    const int f_c  = tid >> 3;          // 0..31 c within chunk
    const int f_q0 = (tid & 7) << 3;    // 0,8,..,56

    auto prefetch = [&](int chunk, int buf) {
        const float* srcc = xn + (size_t)((chunk << 5) + f_c) * 4096 + f_q0;
        const uint32_t dstc = sb + buf * XS_BUF_B +
                              ((f_c * XS_ROWS) * XS_PITCH + 4 + f_q0) * 4;
        #pragma unroll
        for (int r = 0; r < XS_ROWS; r++) {
            const int row = p0 - 1 + r;
            const int pb = ((unsigned)row < 64u) ? 16 : 0;
            const float* src = srcc + row * 64;
            const uint32_t dst = dstc + r * (XS_PITCH * 4);
            asm volatile("cp.async.cg.shared.global [%0], [%1], 16, %2;"
                         :: "r"(dst), "l"(src), "r"(pb));
            asm volatile("cp.async.cg.shared.global [%0], [%1], 16, %2;"
                         :: "r"(dst + 16), "l"(src + 4), "r"(pb));
        }
        asm volatile("cp.async.commit_group;");
    };

    prefetch(0, 0);
    prefetch(1, 1);

    float acc[2][4][4][4];
    #pragma unroll
    for (int nx = 0; nx < 2; nx++)
        #pragma unroll
        for (int mt = 0; mt < 4; mt++)
            #pragma unroll
            for (int nt = 0; nt < 4; nt++)
                #pragma unroll
                for (int e = 0; e < 4; e++) acc[nx][mt][nt][e] = 0.f;

    for (int chunk = 0; chunk < 4; chunk++) {
        if (chunk < 3) asm volatile("cp.async.wait_group 1;");
        else           asm volatile("cp.async.wait_group 0;");
        __syncthreads();

        const uint32_t xb = sb + (chunk & 1) * XS_BUF_B;
        // B base (floats): (tig*6 + wn)*76 + 4 + gid   (c=tig, row=wn, col 4+gid)
        const uint32_t bbase = xb + ((tig * XS_ROWS + wn) * XS_PITCH + 4 + gid) * 4;
        const uint4* abase = (const uint4*)WtFrag + (chunk << 10) + (wm << 7) + lane;

        unsigned areg[2][4][4];
        #pragma unroll
        for (int mt = 0; mt < 4; mt++)
            LDG_A4(areg[0][mt], abase + mt * 32);

        #pragma unroll
        for (int jj = 0; jj < 36; jj++) {
            const int shift = jj >> 2, j = jj & 3;
            const int kh = shift / 3, kw = shift - 3 * kh;
            const int cur = jj & 1, nxt = cur ^ 1;

            const int jn = jj + 1;
            const int aoff = (jn >> 2) * 4096 + (jn & 3) * 256;  // uint4 units

            // first half of next-jj A prefetch
            if (jj < 35) {
                LDG_A4(areg[nxt][0], abase + aoff + 0 * 32);
                LDG_A4(areg[nxt][1], abase + aoff + 1 * 32);
            }

            // shift+j offset in bytes: (kh*76 + kw-1)*4 + j * (8c * 6*76*4)
            const uint32_t bsj = bbase + (kh * XS_PITCH + kw - 1) * 4 + j * 14592;

            // ---- nx = 0 half ----
            {
                const uint32_t bq = bsj;
                unsigned b[4][2];
                #pragma unroll
                for (int nt = 0; nt < 4; nt++) {
                    asm volatile("ld.shared.b32 %0, [%1];" : "=r"(b[nt][0])
                                 : "r"(bq + (nt << 5)));
                    asm volatile("ld.shared.b32 %0, [%1];" : "=r"(b[nt][1])
                                 : "r"(bq + (nt << 5) + 7296));   // c+4
                }
                #pragma unroll
                for (int mt = 0; mt < 4; mt++)
                    #pragma unroll
                    for (int nt = 0; nt < 4; nt++)
                        mma_tf32(acc[0][mt][nt], areg[cur][mt], b[nt]);
            }

            // second half of next-jj A prefetch
            if (jj < 35) {
                LDG_A4(areg[nxt][2], abase + aoff + 2 * 32);
                LDG_A4(areg[nxt][3], abase + aoff + 3 * 32);
            }

            // ---- nx = 1 half ----
            {
                const uint32_t bq = bsj + 128;    // q0 = 32 floats
                unsigned b[4][2];
                #pragma unroll
                for (int nt = 0; nt < 4; nt++) {
                    asm volatile("ld.shared.b32 %0, [%1];" : "=r"(b[nt][0])
                                 : "r"(bq + (nt << 5)));
                    asm volatile("ld.shared.b32 %0, [%1];" : "=r"(b[nt][1])
                                 : "r"(bq + (nt << 5) + 7296));
                }
                #pragma unroll
                for (int mt = 0; mt < 4; mt++)
                    #pragma unroll
                    for (int nt = 0; nt < 4; nt++)
                        mma_tf32(acc[1][mt][nt], areg[cur][mt], b[nt]);
            }
        }

        __syncthreads();
        if (chunk + 2 < 4) prefetch(chunk + 2, chunk & 1);
    }

    // ---- epilogue: +perturbs, store ----
    const size_t nbase = (size_t)n * 128 * 4096;
    const int prow = p0 + wn;
    #pragma unroll
    for (int nx = 0; nx < 2; nx++) {
        #pragma unroll
        for (int mt = 0; mt < 4; mt++) {
            #pragma unroll
            for (int nt = 0; nt < 4; nt++) {
                const int q = (nx << 5) + (nt << 3) + (tig << 1);
                #pragma unroll
                for (int h = 0; h < 2; h++) {
                    const int k = (wm << 6) + (mt << 4) + gid + (h << 3);
                    const size_t o = nbase + (size_t)k * 4096 + prow * 64 + q;
                    float2 pv = *reinterpret_cast<const float2*>(per + o);
                    float2 ov;
                    ov.x = acc[nx][mt][nt][h * 2 + 0] + pv.x;
                    ov.y = acc[nx][mt][nt][h * 2 + 1] + pv.y;
                    *reinterpret_cast<float2*>(out + o) = ov;
                }
            }
        }
    }
}

extern "C" void kernel_launch(void* const* d_in, const int* in_sizes, int n_in,
                              void* d_out, int out_size) {
    const float* x   = (const float*)d_in[0];   // (32,128,64,64)
    const float* W   = (const float*)d_in[1];   // (128,1152)
    const float* per = (const float*)d_in[2];   // (32,128,64,64)
    float* out = (float*)d_out;

    cudaFuncSetAttribute(conv_mma_kernel,
                         cudaFuncAttributeMaxDynamicSharedMemorySize, DYN_SMEM);

    prepack_kernel<<<(NSTAGES * 4096 + 255) / 256, 256>>>(W);
    conv_mma_kernel<<<512, 256, DYN_SMEM>>>(x, per, out);
}